// round 10
// baseline (speedup 1.0000x reference)
#include <cuda_runtime.h>
#include <math.h>

// ---------------------------------------------------------------------------
// Multi-view edge photometric loss.
// Output f32: loss(S,N) | mask(S,N) | black(N) | p2d1(P,2) | p2d2(S,P,2)
// Images re-tiled into a "pair-row" layout: t2[y*W+x] = (img[y][x], img[y+1][x])
// (last row self-paired) so ONE bilinear = 2x LDG.64 instead of 4x LDG.32.
// prep (scan + edge params) and tile fused into one launch (disjoint data).
// ---------------------------------------------------------------------------

#define MAXE 6144
#define NS 4
#define NHV2 20
#define TIMG2_CAP (4 * 1024 * 1024)   // float2 slots (32 MB) — 5*800*800 fits

__device__ float4 g_params4[5 * MAXE * 2];  // per (cam,edge): p0x,p0y,dx,dy | ux,uy,du,dv
__device__ int    g_begin[MAXE];
__device__ float2 g_timg2[TIMG2_CAP];

// ---------------- fused prep+tile: block-range dispatch --------------------
__device__ __forceinline__ void store_prm(int cam, int e, int nE,
                                          float p0x, float p0y,
                                          float dx, float dy, float upscale)
{
    float cx = dy, cy = -dx;
    float nrm = sqrtf(cx * cx + cy * cy);
    float sc = upscale / (nrm + 1e-6f);
    float ux = cx * sc, uy = cy * sc;
    float* p = reinterpret_cast<float*>(&g_params4[((size_t)cam * nE + e) * 2]);
    p[0] = p0x; p[1] = p0y; p[2] = dx; p[3] = dy;
    p[4] = ux;  p[5] = uy;
    p[6] = ux * (1.0f / 9.0f);   // uv delta between the two points of a pair
    p[7] = uy * (1.0f / 9.0f);
}

__global__ void prep_tile_kernel(const int* __restrict__ npe,
                                 const float* __restrict__ sp,
                                 const float* __restrict__ ep,
                                 const float* __restrict__ K,
                                 const float* __restrict__ trans,
                                 const float* __restrict__ imgs,
                                 int n_edges, int num_src, float upscale,
                                 int W, int H, int param_blocks)
{
    int blk = blockIdx.x;
    if (blk == 0) {
        __shared__ int ssum[256];
        int tid = threadIdx.x;
        int chunk = (n_edges + 255) / 256;
        int lo = min(tid * chunk, n_edges);
        int hi = min(lo + chunk, n_edges);
        int local = 0;
        for (int i = lo; i < hi; i++) local += npe[i];
        ssum[tid] = local;
        __syncthreads();
        for (int d = 1; d < 256; d <<= 1) {
            int t = (tid >= d) ? ssum[tid - d] : 0;
            __syncthreads();
            ssum[tid] += t;
            __syncthreads();
        }
        int run = ssum[tid] - local;
        for (int i = lo; i < hi; i++) { g_begin[i] = run; run += npe[i]; }
        return;
    }
    if (blk <= param_blocks) {
        int e = (blk - 1) * blockDim.x + threadIdx.x;
        if (e >= n_edges) return;
        float sx = sp[3 * e], sy = sp[3 * e + 1], sz = sp[3 * e + 2];
        float tx = ep[3 * e], ty = ep[3 * e + 1], tz = ep[3 * e + 2];
        {
            float pzs = K[6] * sx + K[7] * sy + K[8] * sz;
            float us  = (K[0] * sx + K[1] * sy + K[2] * sz) / (pzs + 1e-6f);
            float vs  = (K[3] * sx + K[4] * sy + K[5] * sz) / (pzs + 1e-6f);
            float pzt = K[6] * tx + K[7] * ty + K[8] * tz;
            float ut  = (K[0] * tx + K[1] * ty + K[2] * tz) / (pzt + 1e-6f);
            float vt  = (K[3] * tx + K[4] * ty + K[5] * tz) / (pzt + 1e-6f);
            store_prm(0, e, n_edges, us, vs, ut - us, vt - vs, upscale);
        }
        for (int s = 0; s < num_src; s++) {
            const float* T = trans + 12 * s;
            float pzs = T[8] * sx + T[9] * sy + T[10] * sz + T[11];
            float us  = (T[0] * sx + T[1] * sy + T[2] * sz + T[3]) / (pzs + 1e-6f);
            float vs  = (T[4] * sx + T[5] * sy + T[6] * sz + T[7]) / (pzs + 1e-6f);
            float pzt = T[8] * tx + T[9] * ty + T[10] * tz + T[11];
            float ut  = (T[0] * tx + T[1] * ty + T[2] * tz + T[3]) / (pzt + 1e-6f);
            float vt  = (T[4] * tx + T[5] * ty + T[6] * tz + T[7]) / (pzt + 1e-6f);
            store_prm(1 + s, e, n_edges, us, vs, ut - us, vt - vs, upscale);
        }
        return;
    }
    // tile pass: row-major -> pair-row layout (each row holds y and y+1)
    int perHW = W * H;
    int nimg = num_src + 1;
    int total = nimg * perHW;
    int idx = (blk - 1 - param_blocks) * blockDim.x + threadIdx.x;
    if (idx >= total) return;
    int c = idx / perHW;
    int rem = idx - c * perHW;
    int y = rem / W;
    int x = rem - y * W;
    const float* img = imgs + (size_t)c * perHW;
    float a = img[(size_t)y * W + x];
    int y1 = (y + 1 < H) ? y + 1 : H - 1;
    float bdown = img[(size_t)y1 * W + x];
    g_timg2[(size_t)c * perHW + rem] = make_float2(a, bdown);
}

// ------------------- bilinear sample on pair-row layout --------------------
__device__ __forceinline__ float bilerp_t2(const float2* __restrict__ img2,
                                           float u, float v, int W, int H)
{
    float x = fmaf(u, (float)W, -0.5f);
    float y = fmaf(v, (float)H, -0.5f);
    float x0f = floorf(x), y0f = floorf(y);
    float wx = x - x0f, wy = y - y0f;
    int x0 = max((int)x0f, 0);          // floor <= W-1 guaranteed (u < 1)
    int x1 = min(x0 + 1, W - 1);
    int y0 = max((int)y0f, 0);          // floor <= H-1 guaranteed (v < 1)
    int row = y0 * W;
    float2 c0 = __ldg(img2 + (row + x0));   // (v00, v10)
    float2 c1 = __ldg(img2 + (row + x1));   // (v01, v11)
    float top = fmaf(wx, c1.x - c0.x, c0.x);
    float bot = fmaf(wx, c1.y - c0.y, c0.y);
    return fmaf(wy, bot - top, top);
}

// ----------- point kernel: block/edge, 128 thr, 2 points/thread ------------
__global__ void __launch_bounds__(128, 9)
point_kernel(const int* __restrict__ npe,
             float* __restrict__ out_loss, float* __restrict__ out_mask,
             float* __restrict__ out_black,
             float* __restrict__ out_p2d1, float* __restrict__ out_p2d2,
             int W, int H, int n_edges, int P)
{
    int e = blockIdx.x;
    int tid = threadIdx.x;

    __shared__ float4 sprm4[10];    // 5 cams x {p0x,p0y,dx,dy | ux,uy,du,dv}
    __shared__ float redf[4][5];
    __shared__ unsigned redm[4];

    if (tid < 10) {
        int c = tid >> 1, half = tid & 1;
        sprm4[tid] = g_params4[((size_t)c * n_edges + e) * 2 + half];
    }
    __syncthreads();

    int b = g_begin[e];
    int n = npe[e];
    float inv_nh1 = 1.0f / (float)(n / NHV2 - 1);
    const int perHW = W * H;        // float2 stride per image

    float ls0 = 0.f, ls1 = 0.f, ls2 = 0.f, ls3 = 0.f;
    float bc = 0.f;
    unsigned m = (1u << NS) - 1u;

    float4* o1 = reinterpret_cast<float4*>(out_p2d1) + (b >> 1);
    float4* o2 = reinterpret_cast<float4*>(out_p2d2) + (b >> 1);
    const int strideP = P >> 1;

    int npair = n >> 1;
    // incremental (h, jj): r = h*10 + jj, r advances by 128 = 12*10 + 8
    int h  = tid / 10;
    int jj = tid - h * 10;
    for (int r = tid; r < npair; r += 128) {
        float cx = (float)h * inv_nh1;
        float base = (float)(2 * jj + ((jj < 5) ? -9 : -10));
        float cy0 = base * (1.0f / 9.0f);

        // reference camera: point A via fma, point B via precomputed delta
        float4 qa = sprm4[0], qb = sprm4[1];
        float u0 = fmaf(qa.z, cx, fmaf(qb.x, cy0, qa.x));
        float v0 = fmaf(qa.w, cx, fmaf(qb.y, cy0, qa.y));
        float u1 = u0 + qb.z;
        float v1 = v0 + qb.w;
        bool vm1a = (u0 > 0.f) & (u0 < 1.f) & (v0 > 0.f) & (v0 < 1.f);
        bool vm1b = (u1 > 0.f) & (u1 < 1.f) & (v1 > 0.f) & (v1 < 1.f);
        u0 = fminf(fmaxf(u0, 0.f), 0.999999f);
        v0 = fminf(fmaxf(v0, 0.f), 0.999999f);
        u1 = fminf(fmaxf(u1, 0.f), 0.999999f);
        v1 = fminf(fmaxf(v1, 0.f), 0.999999f);
        o1[r] = make_float4(u0, v0, u1, v1);
        float s1a = bilerp_t2(g_timg2, u0, v0, W, H);
        float s1b = bilerp_t2(g_timg2, u1, v1, W, H);
        if (s1a < 0.01f) bc += 1.f;
        if (s1b < 0.01f) bc += 1.f;

#pragma unroll
        for (int s = 0; s < NS; s++) {
            float4 pa = sprm4[2 * (s + 1)], pb = sprm4[2 * (s + 1) + 1];
            float ua = fmaf(pa.z, cx, fmaf(pb.x, cy0, pa.x));
            float va = fmaf(pa.w, cx, fmaf(pb.y, cy0, pa.y));
            float ub = ua + pb.z;
            float vb = va + pb.w;
            bool oka = vm1a & (ua > 0.f) & (ua < 1.f) & (va > 0.f) & (va < 1.f);
            bool okb = vm1b & (ub > 0.f) & (ub < 1.f) & (vb > 0.f) & (vb < 1.f);
            ua = fminf(fmaxf(ua, 0.f), 0.999999f);
            va = fminf(fmaxf(va, 0.f), 0.999999f);
            ub = fminf(fmaxf(ub, 0.f), 0.999999f);
            vb = fminf(fmaxf(vb, 0.f), 0.999999f);
            o2[s * strideP + r] = make_float4(ua, va, ub, vb);
            const float2* img2 = g_timg2 + (s + 1) * perHW;
            float s2a = bilerp_t2(img2, ua, va, W, H);
            float s2b = bilerp_t2(img2, ub, vb, W, H);
            float da = s2a - s1a;
            float db = s2b - s1b;
            float acc = fmaf(da, da, db * db);
            if (s == 0) ls0 += acc;
            else if (s == 1) ls1 += acc;
            else if (s == 2) ls2 += acc;
            else ls3 += acc;
            if (!(oka && okb)) m &= ~(1u << s);
        }

        jj += 8;
        if (jj >= 10) { jj -= 10; h += 13; } else { h += 12; }
    }

    // warp + block reduce
#pragma unroll
    for (int off = 16; off > 0; off >>= 1) {
        ls0 += __shfl_down_sync(0xFFFFFFFFu, ls0, off);
        ls1 += __shfl_down_sync(0xFFFFFFFFu, ls1, off);
        ls2 += __shfl_down_sync(0xFFFFFFFFu, ls2, off);
        ls3 += __shfl_down_sync(0xFFFFFFFFu, ls3, off);
        bc  += __shfl_down_sync(0xFFFFFFFFu, bc, off);
        m   &= __shfl_down_sync(0xFFFFFFFFu, m, off);
    }
    int lane = tid & 31, warp = tid >> 5;
    if (lane == 0) {
        redf[warp][0] = ls0; redf[warp][1] = ls1;
        redf[warp][2] = ls2; redf[warp][3] = ls3;
        redf[warp][4] = bc;
        redm[warp] = m;
    }
    __syncthreads();
    if (tid == 0) {
        float tls[NS] = {0.f, 0.f, 0.f, 0.f};
        float tbc = 0.f;
        unsigned tm = (1u << NS) - 1u;
        for (int w = 0; w < 4; w++) {
#pragma unroll
            for (int s = 0; s < NS; s++) tls[s] += redf[w][s];
            tbc += redf[w][4];
            tm &= redm[w];
        }
        float cnt = (float)n;
#pragma unroll
        for (int s = 0; s < NS; s++) {
            out_loss[s * n_edges + e] = tls[s] / cnt;
            out_mask[s * n_edges + e] = ((tm >> s) & 1u) ? 1.f : 0.f;
        }
        out_black[e] = ((tbc / cnt) > 0.5f) ? 1.f : 0.f;
    }
}

// ---------------------------------------------------------------------------
extern "C" void kernel_launch(void* const* d_in, const int* in_sizes, int n_in,
                              void* d_out, int out_size)
{
    const float* start = (const float*)d_in[0];
    const float* end_p = (const float*)d_in[1];
    const float* imgs  = (const float*)d_in[2];
    const float* trans = (const float*)d_in[3];
    const float* K     = (const float*)d_in[4];
    const int*   npe   = (const int*)d_in[8];
    float* out = (float*)d_out;

    int n_edges = in_sizes[0] / 3;
    int P       = in_sizes[5];
    int num_src = in_sizes[3] / 12;  // 4
    int nimg    = num_src + 1;
    long long hw = (long long)in_sizes[2] / nimg;
    int W = (int)(sqrt((double)hw) + 0.5);
    int H = (int)(hw / W);

    float* out_loss  = out;
    float* out_mask  = out_loss + (size_t)num_src * n_edges;
    float* out_black = out_mask + (size_t)num_src * n_edges;
    float* out_p2d1  = out_black + n_edges;
    float* out_p2d2  = out_p2d1 + 2 * (size_t)P;

    int param_blocks = (n_edges + 255) / 256;
    int tile_total = nimg * W * H;
    int tile_blocks = (tile_total + 255) / 256;
    prep_tile_kernel<<<1 + param_blocks + tile_blocks, 256>>>(
        npe, start, end_p, K, trans, imgs,
        n_edges, num_src, 10.0f / (float)W, W, H, param_blocks);
    point_kernel<<<n_edges, 128>>>(npe,
                                   out_loss, out_mask, out_black,
                                   out_p2d1, out_p2d2,
                                   W, H, n_edges, P);
}

// round 12
// speedup vs baseline: 1.3122x; 1.3122x over previous
#include <cuda_runtime.h>
#include <math.h>

// ---------------------------------------------------------------------------
// Multi-view edge photometric loss.
// Output f32: loss(S,N) | mask(S,N) | black(N) | p2d1(P,2) | p2d2(S,P,2)
// Images re-tiled (4-row interleave, float): idx(x,y)=(y&~3)*W + 4x + (y&3),
// so a bilinear's 4 corners share 128B sectors (round-7/9 validated layout).
// prep (scan + edge params) and tile fused into one launch (disjoint data).
// ---------------------------------------------------------------------------

#define MAXE 6144
#define NS 4
#define NHV2 20
#define TIMG_CAP (4 * 1024 * 1024)   // floats (16 MB) — 5 x 800 x 800 fits

__device__ float4 g_params4[5 * MAXE * 2];  // per (cam,edge): p0x,p0y,dx,dy | ux,uy,du,dv
__device__ int    g_begin[MAXE];
__device__ float  g_timg[TIMG_CAP];

// ---------------- fused prep+tile: block-range dispatch --------------------
__device__ __forceinline__ void store_prm(int cam, int e, int nE,
                                          float p0x, float p0y,
                                          float dx, float dy, float upscale)
{
    float cx = dy, cy = -dx;
    float nrm = sqrtf(cx * cx + cy * cy);
    float sc = upscale / (nrm + 1e-6f);
    float ux = cx * sc, uy = cy * sc;
    float* p = reinterpret_cast<float*>(&g_params4[((size_t)cam * nE + e) * 2]);
    p[0] = p0x; p[1] = p0y; p[2] = dx; p[3] = dy;
    p[4] = ux;  p[5] = uy;
    p[6] = ux * (1.0f / 9.0f);   // uv delta between the two points of a pair
    p[7] = uy * (1.0f / 9.0f);
}

__global__ void prep_tile_kernel(const int* __restrict__ npe,
                                 const float* __restrict__ sp,
                                 const float* __restrict__ ep,
                                 const float* __restrict__ K,
                                 const float* __restrict__ trans,
                                 const float* __restrict__ imgs,
                                 int n_edges, int num_src, float upscale,
                                 int W, int H, int param_blocks)
{
    int blk = blockIdx.x;
    if (blk == 0) {
        __shared__ int ssum[256];
        int tid = threadIdx.x;
        int chunk = (n_edges + 255) / 256;
        int lo = min(tid * chunk, n_edges);
        int hi = min(lo + chunk, n_edges);
        int local = 0;
        for (int i = lo; i < hi; i++) local += npe[i];
        ssum[tid] = local;
        __syncthreads();
        for (int d = 1; d < 256; d <<= 1) {
            int t = (tid >= d) ? ssum[tid - d] : 0;
            __syncthreads();
            ssum[tid] += t;
            __syncthreads();
        }
        int run = ssum[tid] - local;
        for (int i = lo; i < hi; i++) { g_begin[i] = run; run += npe[i]; }
        return;
    }
    if (blk <= param_blocks) {
        int e = (blk - 1) * blockDim.x + threadIdx.x;
        if (e >= n_edges) return;
        float sx = sp[3 * e], sy = sp[3 * e + 1], sz = sp[3 * e + 2];
        float tx = ep[3 * e], ty = ep[3 * e + 1], tz = ep[3 * e + 2];
        {
            float pzs = K[6] * sx + K[7] * sy + K[8] * sz;
            float us  = (K[0] * sx + K[1] * sy + K[2] * sz) / (pzs + 1e-6f);
            float vs  = (K[3] * sx + K[4] * sy + K[5] * sz) / (pzs + 1e-6f);
            float pzt = K[6] * tx + K[7] * ty + K[8] * tz;
            float ut  = (K[0] * tx + K[1] * ty + K[2] * tz) / (pzt + 1e-6f);
            float vt  = (K[3] * tx + K[4] * ty + K[5] * tz) / (pzt + 1e-6f);
            store_prm(0, e, n_edges, us, vs, ut - us, vt - vs, upscale);
        }
        for (int s = 0; s < num_src; s++) {
            const float* T = trans + 12 * s;
            float pzs = T[8] * sx + T[9] * sy + T[10] * sz + T[11];
            float us  = (T[0] * sx + T[1] * sy + T[2] * sz + T[3]) / (pzs + 1e-6f);
            float vs  = (T[4] * sx + T[5] * sy + T[6] * sz + T[7]) / (pzs + 1e-6f);
            float pzt = T[8] * tx + T[9] * ty + T[10] * tz + T[11];
            float ut  = (T[0] * tx + T[1] * ty + T[2] * tz + T[3]) / (pzt + 1e-6f);
            float vt  = (T[4] * tx + T[5] * ty + T[6] * tz + T[7]) / (pzt + 1e-6f);
            store_prm(1 + s, e, n_edges, us, vs, ut - us, vt - vs, upscale);
        }
        return;
    }
    // tile pass: row-major -> 4-row interleaved
    int G = (H + 3) >> 2;
    int per = G * W;                      // float4 slots per image
    int nimg = num_src + 1;
    int total = nimg * per;
    int idx = (blk - 1 - param_blocks) * blockDim.x + threadIdx.x;
    if (idx >= total) return;
    int c = idx / per;
    int rem = idx - c * per;
    int g = rem / W;
    int x = rem - g * W;
    const float* img = imgs + (size_t)c * W * H;
    float4 v;
    int y0 = g * 4;
    v.x = img[(size_t)y0 * W + x];
    v.y = (y0 + 1 < H) ? img[(size_t)(y0 + 1) * W + x] : 0.f;
    v.z = (y0 + 2 < H) ? img[(size_t)(y0 + 2) * W + x] : 0.f;
    v.w = (y0 + 3 < H) ? img[(size_t)(y0 + 3) * W + x] : 0.f;
    reinterpret_cast<float4*>(g_timg)[(size_t)c * per + rem] = v;
}

// ------------------- bilinear sample on tiled layout -----------------------
// tiled idx(x,y) = (y & ~3)*W + 4x + (y & 3)
__device__ __forceinline__ float bilerp_t(const float* __restrict__ timg,
                                          float u, float v, int W, int H)
{
    float x = fmaf(u, (float)W, -0.5f);
    float y = fmaf(v, (float)H, -0.5f);
    float x0f = floorf(x), y0f = floorf(y);
    float wx = x - x0f, wy = y - y0f;
    int x0 = max((int)x0f, 0);          // floor <= W-1 guaranteed (u < 1)
    int x1 = min(x0 + 1, W - 1);
    int y0 = max((int)y0f, 0);
    int y1 = min(y0 + 1, H - 1);
    int base0 = (y0 & ~3) * W + (y0 & 3);
    int base1 = (y1 & ~3) * W + (y1 & 3);
    int xs0 = x0 << 2, xs1 = x1 << 2;
    float v00 = __ldg(timg + (base0 + xs0));
    float v01 = __ldg(timg + (base0 + xs1));
    float v10 = __ldg(timg + (base1 + xs0));
    float v11 = __ldg(timg + (base1 + xs1));
    float top = fmaf(wx, v01 - v00, v00);
    float bot = fmaf(wx, v11 - v10, v10);
    return fmaf(wy, bot - top, top);
}

// ----------- point kernel: block/edge, 128 thr, 2 points/thread ------------
__global__ void __launch_bounds__(128, 9)
point_kernel(const int* __restrict__ npe,
             float* __restrict__ out_loss, float* __restrict__ out_mask,
             float* __restrict__ out_black,
             float* __restrict__ out_p2d1, float* __restrict__ out_p2d2,
             int W, int H, int n_edges, int P)
{
    int e = blockIdx.x;
    int tid = threadIdx.x;

    __shared__ float4 sprm4[10];    // 5 cams x {p0x,p0y,dx,dy | ux,uy,du,dv}
    __shared__ float redf[4][5];
    __shared__ unsigned redm[4];

    if (tid < 10) {
        int c = tid >> 1, half = tid & 1;
        sprm4[tid] = g_params4[((size_t)c * n_edges + e) * 2 + half];
    }
    __syncthreads();

    int b = g_begin[e];
    int n = npe[e];
    float inv_nh1 = 1.0f / (float)(n / NHV2 - 1);
    const int tstride = ((H + 3) >> 2) * 4 * W;

    float ls0 = 0.f, ls1 = 0.f, ls2 = 0.f, ls3 = 0.f;
    float bc = 0.f;
    unsigned m = (1u << NS) - 1u;

    float4* o1 = reinterpret_cast<float4*>(out_p2d1) + (b >> 1);
    float4* o2 = reinterpret_cast<float4*>(out_p2d2) + (b >> 1);
    const int strideP = P >> 1;

    int npair = n >> 1;
    // incremental (h, jj): r = h*10 + jj, r advances by 128 = 12*10 + 8
    int h  = tid / 10;
    int jj = tid - h * 10;
    for (int r = tid; r < npair; r += 128) {
        float cx = (float)h * inv_nh1;
        float base = (float)(2 * jj + ((jj < 5) ? -9 : -10));
        float cy0 = base * (1.0f / 9.0f);

        // reference camera: point A via fma, point B via precomputed delta
        float4 qa = sprm4[0], qb = sprm4[1];
        float u0 = fmaf(qa.z, cx, fmaf(qb.x, cy0, qa.x));
        float v0 = fmaf(qa.w, cx, fmaf(qb.y, cy0, qa.y));
        float u1 = u0 + qb.z;
        float v1 = v0 + qb.w;
        bool vm1a = (u0 > 0.f) & (u0 < 1.f) & (v0 > 0.f) & (v0 < 1.f);
        bool vm1b = (u1 > 0.f) & (u1 < 1.f) & (v1 > 0.f) & (v1 < 1.f);
        u0 = fminf(fmaxf(u0, 0.f), 0.999999f);
        v0 = fminf(fmaxf(v0, 0.f), 0.999999f);
        u1 = fminf(fmaxf(u1, 0.f), 0.999999f);
        v1 = fminf(fmaxf(v1, 0.f), 0.999999f);
        o1[r] = make_float4(u0, v0, u1, v1);
        float s1a = bilerp_t(g_timg, u0, v0, W, H);
        float s1b = bilerp_t(g_timg, u1, v1, W, H);
        bc += (s1a < 0.01f) ? 1.f : 0.f;
        bc += (s1b < 0.01f) ? 1.f : 0.f;

#pragma unroll
        for (int s = 0; s < NS; s++) {
            float4 pa = sprm4[2 * (s + 1)], pb = sprm4[2 * (s + 1) + 1];
            float ua = fmaf(pa.z, cx, fmaf(pb.x, cy0, pa.x));
            float va = fmaf(pa.w, cx, fmaf(pb.y, cy0, pa.y));
            float ub = ua + pb.z;
            float vb = va + pb.w;
            bool oka = vm1a & (ua > 0.f) & (ua < 1.f) & (va > 0.f) & (va < 1.f);
            bool okb = vm1b & (ub > 0.f) & (ub < 1.f) & (vb > 0.f) & (vb < 1.f);
            ua = fminf(fmaxf(ua, 0.f), 0.999999f);
            va = fminf(fmaxf(va, 0.f), 0.999999f);
            ub = fminf(fmaxf(ub, 0.f), 0.999999f);
            vb = fminf(fmaxf(vb, 0.f), 0.999999f);
            o2[s * strideP + r] = make_float4(ua, va, ub, vb);
            const float* img = g_timg + (s + 1) * tstride;
            float s2a = bilerp_t(img, ua, va, W, H);
            float s2b = bilerp_t(img, ub, vb, W, H);
            float da = s2a - s1a;
            float db = s2b - s1b;
            float acc = fmaf(da, da, db * db);
            if (s == 0) ls0 += acc;
            else if (s == 1) ls1 += acc;
            else if (s == 2) ls2 += acc;
            else ls3 += acc;
            if (!(oka && okb)) m &= ~(1u << s);
        }

        jj += 8;
        if (jj >= 10) { jj -= 10; h += 13; } else { h += 12; }
    }

    // warp + block reduce
#pragma unroll
    for (int off = 16; off > 0; off >>= 1) {
        ls0 += __shfl_down_sync(0xFFFFFFFFu, ls0, off);
        ls1 += __shfl_down_sync(0xFFFFFFFFu, ls1, off);
        ls2 += __shfl_down_sync(0xFFFFFFFFu, ls2, off);
        ls3 += __shfl_down_sync(0xFFFFFFFFu, ls3, off);
        bc  += __shfl_down_sync(0xFFFFFFFFu, bc, off);
        m   &= __shfl_down_sync(0xFFFFFFFFu, m, off);
    }
    int lane = tid & 31, warp = tid >> 5;
    if (lane == 0) {
        redf[warp][0] = ls0; redf[warp][1] = ls1;
        redf[warp][2] = ls2; redf[warp][3] = ls3;
        redf[warp][4] = bc;
        redm[warp] = m;
    }
    __syncthreads();
    if (tid == 0) {
        float tls[NS] = {0.f, 0.f, 0.f, 0.f};
        float tbc = 0.f;
        unsigned tm = (1u << NS) - 1u;
        for (int w = 0; w < 4; w++) {
#pragma unroll
            for (int s = 0; s < NS; s++) tls[s] += redf[w][s];
            tbc += redf[w][4];
            tm &= redm[w];
        }
        float cnt = (float)n;
#pragma unroll
        for (int s = 0; s < NS; s++) {
            out_loss[s * n_edges + e] = tls[s] / cnt;
            out_mask[s * n_edges + e] = ((tm >> s) & 1u) ? 1.f : 0.f;
        }
        out_black[e] = ((tbc / cnt) > 0.5f) ? 1.f : 0.f;
    }
}

// ---------------------------------------------------------------------------
extern "C" void kernel_launch(void* const* d_in, const int* in_sizes, int n_in,
                              void* d_out, int out_size)
{
    const float* start = (const float*)d_in[0];
    const float* end_p = (const float*)d_in[1];
    const float* imgs  = (const float*)d_in[2];
    const float* trans = (const float*)d_in[3];
    const float* K     = (const float*)d_in[4];
    const int*   npe   = (const int*)d_in[8];
    float* out = (float*)d_out;

    int n_edges = in_sizes[0] / 3;
    int P       = in_sizes[5];
    int num_src = in_sizes[3] / 12;  // 4
    int nimg    = num_src + 1;
    long long hw = (long long)in_sizes[2] / nimg;
    int W = (int)(sqrt((double)hw) + 0.5);
    int H = (int)(hw / W);

    float* out_loss  = out;
    float* out_mask  = out_loss + (size_t)num_src * n_edges;
    float* out_black = out_mask + (size_t)num_src * n_edges;
    float* out_p2d1  = out_black + n_edges;
    float* out_p2d2  = out_p2d1 + 2 * (size_t)P;

    int param_blocks = (n_edges + 255) / 256;
    int G = (H + 3) >> 2;
    int tile_total = nimg * G * W;
    int tile_blocks = (tile_total + 255) / 256;
    prep_tile_kernel<<<1 + param_blocks + tile_blocks, 256>>>(
        npe, start, end_p, K, trans, imgs,
        n_edges, num_src, 10.0f / (float)W, W, H, param_blocks);
    point_kernel<<<n_edges, 128>>>(npe,
                                   out_loss, out_mask, out_black,
                                   out_p2d1, out_p2d2,
                                   W, H, n_edges, P);
}

// round 13
// speedup vs baseline: 1.3371x; 1.0190x over previous
#include <cuda_runtime.h>
#include <math.h>

// ---------------------------------------------------------------------------
// Multi-view edge photometric loss.
// Output f32: loss(S,N) | mask(S,N) | black(N) | p2d1(P,2) | p2d2(S,P,2)
// Images re-tiled (4-row interleave, float): idx(x,y)=(y&~3)*W + 4x + (y&3).
// uv clamping done via FFMA.SAT (saturate folded into the projection fma);
// validity masks via float min/max on the saturated coords.
// ---------------------------------------------------------------------------

#define MAXE 6144
#define NS 4
#define NHV2 20
#define TIMG_CAP (4 * 1024 * 1024)   // floats (16 MB) — 5 x 800 x 800 fits

__device__ float4 g_params4[5 * MAXE * 2];  // per (cam,edge): p0x,p0y,dx,dy | ux,uy,-,-
__device__ int    g_begin[MAXE];
__device__ float  g_timg[TIMG_CAP];

// ---------------- fused prep+tile: block-range dispatch --------------------
__device__ __forceinline__ void store_prm(int cam, int e, int nE,
                                          float p0x, float p0y,
                                          float dx, float dy, float upscale)
{
    float cx = dy, cy = -dx;
    float nrm = sqrtf(cx * cx + cy * cy);
    float sc = upscale / (nrm + 1e-6f);
    float* p = reinterpret_cast<float*>(&g_params4[((size_t)cam * nE + e) * 2]);
    p[0] = p0x; p[1] = p0y; p[2] = dx; p[3] = dy;
    p[4] = cx * sc; p[5] = cy * sc; p[6] = 0.f; p[7] = 0.f;
}

__global__ void prep_tile_kernel(const int* __restrict__ npe,
                                 const float* __restrict__ sp,
                                 const float* __restrict__ ep,
                                 const float* __restrict__ K,
                                 const float* __restrict__ trans,
                                 const float* __restrict__ imgs,
                                 int n_edges, int num_src, float upscale,
                                 int W, int H, int param_blocks)
{
    int blk = blockIdx.x;
    if (blk == 0) {
        __shared__ int ssum[256];
        int tid = threadIdx.x;
        int chunk = (n_edges + 255) / 256;
        int lo = min(tid * chunk, n_edges);
        int hi = min(lo + chunk, n_edges);
        int local = 0;
        for (int i = lo; i < hi; i++) local += npe[i];
        ssum[tid] = local;
        __syncthreads();
        for (int d = 1; d < 256; d <<= 1) {
            int t = (tid >= d) ? ssum[tid - d] : 0;
            __syncthreads();
            ssum[tid] += t;
            __syncthreads();
        }
        int run = ssum[tid] - local;
        for (int i = lo; i < hi; i++) { g_begin[i] = run; run += npe[i]; }
        return;
    }
    if (blk <= param_blocks) {
        int e = (blk - 1) * blockDim.x + threadIdx.x;
        if (e >= n_edges) return;
        float sx = sp[3 * e], sy = sp[3 * e + 1], sz = sp[3 * e + 2];
        float tx = ep[3 * e], ty = ep[3 * e + 1], tz = ep[3 * e + 2];
        {
            float pzs = K[6] * sx + K[7] * sy + K[8] * sz;
            float us  = (K[0] * sx + K[1] * sy + K[2] * sz) / (pzs + 1e-6f);
            float vs  = (K[3] * sx + K[4] * sy + K[5] * sz) / (pzs + 1e-6f);
            float pzt = K[6] * tx + K[7] * ty + K[8] * tz;
            float ut  = (K[0] * tx + K[1] * ty + K[2] * tz) / (pzt + 1e-6f);
            float vt  = (K[3] * tx + K[4] * ty + K[5] * tz) / (pzt + 1e-6f);
            store_prm(0, e, n_edges, us, vs, ut - us, vt - vs, upscale);
        }
        for (int s = 0; s < num_src; s++) {
            const float* T = trans + 12 * s;
            float pzs = T[8] * sx + T[9] * sy + T[10] * sz + T[11];
            float us  = (T[0] * sx + T[1] * sy + T[2] * sz + T[3]) / (pzs + 1e-6f);
            float vs  = (T[4] * sx + T[5] * sy + T[6] * sz + T[7]) / (pzs + 1e-6f);
            float pzt = T[8] * tx + T[9] * ty + T[10] * tz + T[11];
            float ut  = (T[0] * tx + T[1] * ty + T[2] * tz + T[3]) / (pzt + 1e-6f);
            float vt  = (T[4] * tx + T[5] * ty + T[6] * tz + T[7]) / (pzt + 1e-6f);
            store_prm(1 + s, e, n_edges, us, vs, ut - us, vt - vs, upscale);
        }
        return;
    }
    // tile pass: row-major -> 4-row interleaved
    int G = (H + 3) >> 2;
    int per = G * W;                      // float4 slots per image
    int nimg = num_src + 1;
    int total = nimg * per;
    int idx = (blk - 1 - param_blocks) * blockDim.x + threadIdx.x;
    if (idx >= total) return;
    int c = idx / per;
    int rem = idx - c * per;
    int g = rem / W;
    int x = rem - g * W;
    const float* img = imgs + (size_t)c * W * H;
    float4 v;
    int y0 = g * 4;
    v.x = img[(size_t)y0 * W + x];
    v.y = (y0 + 1 < H) ? img[(size_t)(y0 + 1) * W + x] : 0.f;
    v.z = (y0 + 2 < H) ? img[(size_t)(y0 + 2) * W + x] : 0.f;
    v.w = (y0 + 3 < H) ? img[(size_t)(y0 + 3) * W + x] : 0.f;
    reinterpret_cast<float4*>(g_timg)[(size_t)c * per + rem] = v;
}

// ------------------- bilinear sample on tiled layout -----------------------
// tiled idx(x,y) = (y & ~3)*W + 4x + (y & 3); u,v in [0,1] (saturated)
__device__ __forceinline__ float bilerp_t(const float* __restrict__ timg,
                                          float u, float v, int W, int H)
{
    float x = fmaf(u, (float)W, -0.5f);
    float y = fmaf(v, (float)H, -0.5f);
    float x0f = floorf(x), y0f = floorf(y);
    float wx = x - x0f, wy = y - y0f;
    int x0 = max((int)x0f, 0);
    int x1 = min(x0 + 1, W - 1);      // u=1 -> x0=W-1, x1=W-1 (x0==x1, wx moot)
    int y0 = max((int)y0f, 0);
    int y1 = min(y0 + 1, H - 1);
    int base0 = (y0 & ~3) * W + (y0 & 3);
    int base1 = (y1 & ~3) * W + (y1 & 3);
    int xs0 = x0 << 2, xs1 = x1 << 2;
    float v00 = __ldg(timg + (base0 + xs0));
    float v01 = __ldg(timg + (base0 + xs1));
    float v10 = __ldg(timg + (base1 + xs0));
    float v11 = __ldg(timg + (base1 + xs1));
    float top = fmaf(wx, v01 - v00, v00);
    float bot = fmaf(wx, v11 - v10, v10);
    return fmaf(wy, bot - top, top);
}

// ----------- point kernel: block/edge, 128 thr, 2 points/thread ------------
__global__ void __launch_bounds__(128, 9)
point_kernel(const int* __restrict__ npe,
             float* __restrict__ out_loss, float* __restrict__ out_mask,
             float* __restrict__ out_black,
             float* __restrict__ out_p2d1, float* __restrict__ out_p2d2,
             int W, int H, int n_edges, int P)
{
    int e = blockIdx.x;
    int tid = threadIdx.x;

    __shared__ float4 sprm4[10];    // 5 cams x {p0x,p0y,dx,dy | ux,uy,-,-}
    __shared__ float redf[4][5];
    __shared__ unsigned redm[4];

    if (tid < 10) {
        int c = tid >> 1, half = tid & 1;
        sprm4[tid] = g_params4[((size_t)c * n_edges + e) * 2 + half];
    }
    __syncthreads();

    int b = g_begin[e];
    int n = npe[e];
    float inv_nh1 = 1.0f / (float)(n / NHV2 - 1);
    const int tstride = ((H + 3) >> 2) * 4 * W;

    float ls0 = 0.f, ls1 = 0.f, ls2 = 0.f, ls3 = 0.f;
    float bc = 0.f;
    unsigned m = (1u << NS) - 1u;

    float4* o1 = reinterpret_cast<float4*>(out_p2d1) + (b >> 1);
    float4* o2 = reinterpret_cast<float4*>(out_p2d2) + (b >> 1);
    const int strideP = P >> 1;

    int npair = n >> 1;
    // incremental (h, jj): r = h*10 + jj, r advances by 128 = 12*10 + 8
    int h  = tid / 10;
    int jj = tid - h * 10;
    for (int r = tid; r < npair; r += 128) {
        float cx = (float)h * inv_nh1;
        float base = (float)(2 * jj + ((jj < 5) ? -9 : -10));
        float cy0 = base * (1.0f / 9.0f);
        float cy1 = (base + 1.0f) * (1.0f / 9.0f);

        // reference camera: FFMA.SAT projections
        float4 qa = sprm4[0], qb = sprm4[1];
        float u0 = __saturatef(fmaf(qa.z, cx, fmaf(qb.x, cy0, qa.x)));
        float v0 = __saturatef(fmaf(qa.w, cx, fmaf(qb.y, cy0, qa.y)));
        float u1 = __saturatef(fmaf(qa.z, cx, fmaf(qb.x, cy1, qa.x)));
        float v1 = __saturatef(fmaf(qa.w, cx, fmaf(qb.y, cy1, qa.y)));
        // validity: all 4 coords strictly interior <=> min>0 && max<1
        float mn1 = fminf(fminf(u0, v0), fminf(u1, v1));
        float mx1 = fmaxf(fmaxf(u0, v0), fmaxf(u1, v1));
        o1[r] = make_float4(u0, v0, u1, v1);
        float s1a = bilerp_t(g_timg, u0, v0, W, H);
        float s1b = bilerp_t(g_timg, u1, v1, W, H);
        bc += (s1a < 0.01f) ? 1.f : 0.f;
        bc += (s1b < 0.01f) ? 1.f : 0.f;

#pragma unroll
        for (int s = 0; s < NS; s++) {
            float4 pa = sprm4[2 * (s + 1)], pb = sprm4[2 * (s + 1) + 1];
            float ua = __saturatef(fmaf(pa.z, cx, fmaf(pb.x, cy0, pa.x)));
            float va = __saturatef(fmaf(pa.w, cx, fmaf(pb.y, cy0, pa.y)));
            float ub = __saturatef(fmaf(pa.z, cx, fmaf(pb.x, cy1, pa.x)));
            float vb = __saturatef(fmaf(pa.w, cx, fmaf(pb.y, cy1, pa.y)));
            float cmn = fminf(mn1, fminf(fminf(ua, va), fminf(ub, vb)));
            float cmx = fmaxf(mx1, fmaxf(fmaxf(ua, va), fmaxf(ub, vb)));
            o2[s * strideP + r] = make_float4(ua, va, ub, vb);
            const float* img = g_timg + (s + 1) * tstride;
            float s2a = bilerp_t(img, ua, va, W, H);
            float s2b = bilerp_t(img, ub, vb, W, H);
            float da = s2a - s1a;
            float db = s2b - s1b;
            float acc = fmaf(da, da, db * db);
            if (s == 0) ls0 += acc;
            else if (s == 1) ls1 += acc;
            else if (s == 2) ls2 += acc;
            else ls3 += acc;
            if (!((cmn > 0.f) & (cmx < 1.f))) m &= ~(1u << s);
        }

        jj += 8;
        if (jj >= 10) { jj -= 10; h += 13; } else { h += 12; }
    }

    // warp + block reduce
#pragma unroll
    for (int off = 16; off > 0; off >>= 1) {
        ls0 += __shfl_down_sync(0xFFFFFFFFu, ls0, off);
        ls1 += __shfl_down_sync(0xFFFFFFFFu, ls1, off);
        ls2 += __shfl_down_sync(0xFFFFFFFFu, ls2, off);
        ls3 += __shfl_down_sync(0xFFFFFFFFu, ls3, off);
        bc  += __shfl_down_sync(0xFFFFFFFFu, bc, off);
        m   &= __shfl_down_sync(0xFFFFFFFFu, m, off);
    }
    int lane = tid & 31, warp = tid >> 5;
    if (lane == 0) {
        redf[warp][0] = ls0; redf[warp][1] = ls1;
        redf[warp][2] = ls2; redf[warp][3] = ls3;
        redf[warp][4] = bc;
        redm[warp] = m;
    }
    __syncthreads();
    if (tid == 0) {
        float tls[NS] = {0.f, 0.f, 0.f, 0.f};
        float tbc = 0.f;
        unsigned tm = (1u << NS) - 1u;
        for (int w = 0; w < 4; w++) {
#pragma unroll
            for (int s = 0; s < NS; s++) tls[s] += redf[w][s];
            tbc += redf[w][4];
            tm &= redm[w];
        }
        float cnt = (float)n;
#pragma unroll
        for (int s = 0; s < NS; s++) {
            out_loss[s * n_edges + e] = tls[s] / cnt;
            out_mask[s * n_edges + e] = ((tm >> s) & 1u) ? 1.f : 0.f;
        }
        out_black[e] = ((tbc / cnt) > 0.5f) ? 1.f : 0.f;
    }
}

// ---------------------------------------------------------------------------
extern "C" void kernel_launch(void* const* d_in, const int* in_sizes, int n_in,
                              void* d_out, int out_size)
{
    const float* start = (const float*)d_in[0];
    const float* end_p = (const float*)d_in[1];
    const float* imgs  = (const float*)d_in[2];
    const float* trans = (const float*)d_in[3];
    const float* K     = (const float*)d_in[4];
    const int*   npe   = (const int*)d_in[8];
    float* out = (float*)d_out;

    int n_edges = in_sizes[0] / 3;
    int P       = in_sizes[5];
    int num_src = in_sizes[3] / 12;  // 4
    int nimg    = num_src + 1;
    long long hw = (long long)in_sizes[2] / nimg;
    int W = (int)(sqrt((double)hw) + 0.5);
    int H = (int)(hw / W);

    float* out_loss  = out;
    float* out_mask  = out_loss + (size_t)num_src * n_edges;
    float* out_black = out_mask + (size_t)num_src * n_edges;
    float* out_p2d1  = out_black + n_edges;
    float* out_p2d2  = out_p2d1 + 2 * (size_t)P;

    int param_blocks = (n_edges + 255) / 256;
    int G = (H + 3) >> 2;
    int tile_total = nimg * G * W;
    int tile_blocks = (tile_total + 255) / 256;
    prep_tile_kernel<<<1 + param_blocks + tile_blocks, 256>>>(
        npe, start, end_p, K, trans, imgs,
        n_edges, num_src, 10.0f / (float)W, W, H, param_blocks);
    point_kernel<<<n_edges, 128>>>(npe,
                                   out_loss, out_mask, out_black,
                                   out_p2d1, out_p2d2,
                                   W, H, n_edges, P);
}

// round 16
// speedup vs baseline: 1.4234x; 1.0645x over previous
#include <cuda_runtime.h>
#include <math.h>

// ---------------------------------------------------------------------------
// Multi-view edge photometric loss.
// Output f32: loss(S,N) | mask(S,N) | black(N) | p2d1(P,2) | p2d2(S,P,2)
// Images re-tiled (4-row interleave, float): idx(x,y)=(y&~3)*W + 4x + (y&3).
// uv clamping via FFMA.SAT; validity masks via float min/max.
// Output stores use st.global.cs (streaming) so they don't evict the tiled
// images from L2 (outputs are write-once, never re-read).
// ---------------------------------------------------------------------------

#define MAXE 6144
#define NS 4
#define NHV2 20
#define TIMG_CAP (4 * 1024 * 1024)   // floats (16 MB) — 5 x 800 x 800 fits

__device__ float4 g_params4[5 * MAXE * 2];  // per (cam,edge): p0x,p0y,dx,dy | ux,uy,-,-
__device__ int    g_begin[MAXE];
__device__ float  g_timg[TIMG_CAP];

__device__ __forceinline__ void stcs4(float4* p, float4 v)
{
    __stcs(p, v);
}

// ---------------- fused prep+tile: block-range dispatch --------------------
__device__ __forceinline__ void store_prm(int cam, int e, int nE,
                                          float p0x, float p0y,
                                          float dx, float dy, float upscale)
{
    float cx = dy, cy = -dx;
    float nrm = sqrtf(cx * cx + cy * cy);
    float sc = upscale / (nrm + 1e-6f);
    float* p = reinterpret_cast<float*>(&g_params4[((size_t)cam * nE + e) * 2]);
    p[0] = p0x; p[1] = p0y; p[2] = dx; p[3] = dy;
    p[4] = cx * sc; p[5] = cy * sc; p[6] = 0.f; p[7] = 0.f;
}

__global__ void prep_tile_kernel(const int* __restrict__ npe,
                                 const float* __restrict__ sp,
                                 const float* __restrict__ ep,
                                 const float* __restrict__ K,
                                 const float* __restrict__ trans,
                                 const float* __restrict__ imgs,
                                 int n_edges, int num_src, float upscale,
                                 int W, int H, int param_blocks)
{
    int blk = blockIdx.x;
    if (blk == 0) {
        __shared__ int ssum[256];
        int tid = threadIdx.x;
        int chunk = (n_edges + 255) / 256;
        int lo = min(tid * chunk, n_edges);
        int hi = min(lo + chunk, n_edges);
        int local = 0;
        for (int i = lo; i < hi; i++) local += npe[i];
        ssum[tid] = local;
        __syncthreads();
        for (int d = 1; d < 256; d <<= 1) {
            int t = (tid >= d) ? ssum[tid - d] : 0;
            __syncthreads();
            ssum[tid] += t;
            __syncthreads();
        }
        int run = ssum[tid] - local;
        for (int i = lo; i < hi; i++) { g_begin[i] = run; run += npe[i]; }
        return;
    }
    if (blk <= param_blocks) {
        int e = (blk - 1) * blockDim.x + threadIdx.x;
        if (e >= n_edges) return;
        float sx = sp[3 * e], sy = sp[3 * e + 1], sz = sp[3 * e + 2];
        float tx = ep[3 * e], ty = ep[3 * e + 1], tz = ep[3 * e + 2];
        {
            float pzs = K[6] * sx + K[7] * sy + K[8] * sz;
            float us  = (K[0] * sx + K[1] * sy + K[2] * sz) / (pzs + 1e-6f);
            float vs  = (K[3] * sx + K[4] * sy + K[5] * sz) / (pzs + 1e-6f);
            float pzt = K[6] * tx + K[7] * ty + K[8] * tz;
            float ut  = (K[0] * tx + K[1] * ty + K[2] * tz) / (pzt + 1e-6f);
            float vt  = (K[3] * tx + K[4] * ty + K[5] * tz) / (pzt + 1e-6f);
            store_prm(0, e, n_edges, us, vs, ut - us, vt - vs, upscale);
        }
        for (int s = 0; s < num_src; s++) {
            const float* T = trans + 12 * s;
            float pzs = T[8] * sx + T[9] * sy + T[10] * sz + T[11];
            float us  = (T[0] * sx + T[1] * sy + T[2] * sz + T[3]) / (pzs + 1e-6f);
            float vs  = (T[4] * sx + T[5] * sy + T[6] * sz + T[7]) / (pzs + 1e-6f);
            float pzt = T[8] * tx + T[9] * ty + T[10] * tz + T[11];
            float ut  = (T[0] * tx + T[1] * ty + T[2] * tz + T[3]) / (pzt + 1e-6f);
            float vt  = (T[4] * tx + T[5] * ty + T[6] * tz + T[7]) / (pzt + 1e-6f);
            store_prm(1 + s, e, n_edges, us, vs, ut - us, vt - vs, upscale);
        }
        return;
    }
    // tile pass: row-major -> 4-row interleaved
    int G = (H + 3) >> 2;
    int per = G * W;                      // float4 slots per image
    int nimg = num_src + 1;
    int total = nimg * per;
    int idx = (blk - 1 - param_blocks) * blockDim.x + threadIdx.x;
    if (idx >= total) return;
    int c = idx / per;
    int rem = idx - c * per;
    int g = rem / W;
    int x = rem - g * W;
    const float* img = imgs + (size_t)c * W * H;
    float4 v;
    int y0 = g * 4;
    v.x = img[(size_t)y0 * W + x];
    v.y = (y0 + 1 < H) ? img[(size_t)(y0 + 1) * W + x] : 0.f;
    v.z = (y0 + 2 < H) ? img[(size_t)(y0 + 2) * W + x] : 0.f;
    v.w = (y0 + 3 < H) ? img[(size_t)(y0 + 3) * W + x] : 0.f;
    reinterpret_cast<float4*>(g_timg)[(size_t)c * per + rem] = v;
}

// ------------------- bilinear sample on tiled layout -----------------------
// tiled idx(x,y) = (y & ~3)*W + 4x + (y & 3); u,v in [0,1] (saturated)
__device__ __forceinline__ float bilerp_t(const float* __restrict__ timg,
                                          float u, float v, int W, int H)
{
    float x = fmaf(u, (float)W, -0.5f);
    float y = fmaf(v, (float)H, -0.5f);
    float x0f = floorf(x), y0f = floorf(y);
    float wx = x - x0f, wy = y - y0f;
    int x0 = max((int)x0f, 0);
    int x1 = min(x0 + 1, W - 1);      // u=1 -> x0=x1=W-1 (wx moot)
    int y0 = max((int)y0f, 0);
    int y1 = min(y0 + 1, H - 1);
    int base0 = (y0 & ~3) * W + (y0 & 3);
    int base1 = (y1 & ~3) * W + (y1 & 3);
    int xs0 = x0 << 2, xs1 = x1 << 2;
    float v00 = __ldg(timg + (base0 + xs0));
    float v01 = __ldg(timg + (base0 + xs1));
    float v10 = __ldg(timg + (base1 + xs0));
    float v11 = __ldg(timg + (base1 + xs1));
    float top = fmaf(wx, v01 - v00, v00);
    float bot = fmaf(wx, v11 - v10, v10);
    return fmaf(wy, bot - top, top);
}

// ----------- point kernel: block/edge, 128 thr, 2 points/thread ------------
__global__ void __launch_bounds__(128, 9)
point_kernel(const int* __restrict__ npe,
             float* __restrict__ out_loss, float* __restrict__ out_mask,
             float* __restrict__ out_black,
             float* __restrict__ out_p2d1, float* __restrict__ out_p2d2,
             int W, int H, int n_edges, int P)
{
    int e = blockIdx.x;
    int tid = threadIdx.x;

    __shared__ float4 sprm4[10];    // 5 cams x {p0x,p0y,dx,dy | ux,uy,-,-}
    __shared__ float redf[4][5];
    __shared__ unsigned redm[4];

    if (tid < 10) {
        int c = tid >> 1, half = tid & 1;
        sprm4[tid] = g_params4[((size_t)c * n_edges + e) * 2 + half];
    }
    __syncthreads();

    int b = g_begin[e];
    int n = npe[e];
    float inv_nh1 = 1.0f / (float)(n / NHV2 - 1);
    const int tstride = ((H + 3) >> 2) * 4 * W;

    float ls0 = 0.f, ls1 = 0.f, ls2 = 0.f, ls3 = 0.f;
    float bc = 0.f;
    unsigned m = (1u << NS) - 1u;

    float4* o1 = reinterpret_cast<float4*>(out_p2d1) + (b >> 1);
    float4* o2 = reinterpret_cast<float4*>(out_p2d2) + (b >> 1);
    const int strideP = P >> 1;

    int npair = n >> 1;
    // incremental (h, jj): r = h*10 + jj, r advances by 128 = 12*10 + 8
    int h  = tid / 10;
    int jj = tid - h * 10;
    for (int r = tid; r < npair; r += 128) {
        float cx = (float)h * inv_nh1;
        float base = (float)(2 * jj + ((jj < 5) ? -9 : -10));
        float cy0 = base * (1.0f / 9.0f);
        float cy1 = (base + 1.0f) * (1.0f / 9.0f);

        // reference camera: FFMA.SAT projections
        float4 qa = sprm4[0], qb = sprm4[1];
        float u0 = __saturatef(fmaf(qa.z, cx, fmaf(qb.x, cy0, qa.x)));
        float v0 = __saturatef(fmaf(qa.w, cx, fmaf(qb.y, cy0, qa.y)));
        float u1 = __saturatef(fmaf(qa.z, cx, fmaf(qb.x, cy1, qa.x)));
        float v1 = __saturatef(fmaf(qa.w, cx, fmaf(qb.y, cy1, qa.y)));
        float mn1 = fminf(fminf(u0, v0), fminf(u1, v1));
        float mx1 = fmaxf(fmaxf(u0, v0), fmaxf(u1, v1));
        stcs4(o1 + r, make_float4(u0, v0, u1, v1));
        float s1a = bilerp_t(g_timg, u0, v0, W, H);
        float s1b = bilerp_t(g_timg, u1, v1, W, H);
        bc += (s1a < 0.01f) ? 1.f : 0.f;
        bc += (s1b < 0.01f) ? 1.f : 0.f;

#pragma unroll
        for (int s = 0; s < NS; s++) {
            float4 pa = sprm4[2 * (s + 1)], pb = sprm4[2 * (s + 1) + 1];
            float ua = __saturatef(fmaf(pa.z, cx, fmaf(pb.x, cy0, pa.x)));
            float va = __saturatef(fmaf(pa.w, cx, fmaf(pb.y, cy0, pa.y)));
            float ub = __saturatef(fmaf(pa.z, cx, fmaf(pb.x, cy1, pa.x)));
            float vb = __saturatef(fmaf(pa.w, cx, fmaf(pb.y, cy1, pa.y)));
            float cmn = fminf(mn1, fminf(fminf(ua, va), fminf(ub, vb)));
            float cmx = fmaxf(mx1, fmaxf(fmaxf(ua, va), fmaxf(ub, vb)));
            stcs4(o2 + (s * strideP + r), make_float4(ua, va, ub, vb));
            const float* img = g_timg + (s + 1) * tstride;
            float s2a = bilerp_t(img, ua, va, W, H);
            float s2b = bilerp_t(img, ub, vb, W, H);
            float da = s2a - s1a;
            float db = s2b - s1b;
            float acc = fmaf(da, da, db * db);
            if (s == 0) ls0 += acc;
            else if (s == 1) ls1 += acc;
            else if (s == 2) ls2 += acc;
            else ls3 += acc;
            if (!((cmn > 0.f) & (cmx < 1.f))) m &= ~(1u << s);
        }

        jj += 8;
        if (jj >= 10) { jj -= 10; h += 13; } else { h += 12; }
    }

    // warp + block reduce
#pragma unroll
    for (int off = 16; off > 0; off >>= 1) {
        ls0 += __shfl_down_sync(0xFFFFFFFFu, ls0, off);
        ls1 += __shfl_down_sync(0xFFFFFFFFu, ls1, off);
        ls2 += __shfl_down_sync(0xFFFFFFFFu, ls2, off);
        ls3 += __shfl_down_sync(0xFFFFFFFFu, ls3, off);
        bc  += __shfl_down_sync(0xFFFFFFFFu, bc, off);
        m   &= __shfl_down_sync(0xFFFFFFFFu, m, off);
    }
    int lane = tid & 31, warp = tid >> 5;
    if (lane == 0) {
        redf[warp][0] = ls0; redf[warp][1] = ls1;
        redf[warp][2] = ls2; redf[warp][3] = ls3;
        redf[warp][4] = bc;
        redm[warp] = m;
    }
    __syncthreads();
    if (tid == 0) {
        float tls[NS] = {0.f, 0.f, 0.f, 0.f};
        float tbc = 0.f;
        unsigned tm = (1u << NS) - 1u;
        for (int w = 0; w < 4; w++) {
#pragma unroll
            for (int s = 0; s < NS; s++) tls[s] += redf[w][s];
            tbc += redf[w][4];
            tm &= redm[w];
        }
        float cnt = (float)n;
#pragma unroll
        for (int s = 0; s < NS; s++) {
            out_loss[s * n_edges + e] = tls[s] / cnt;
            out_mask[s * n_edges + e] = ((tm >> s) & 1u) ? 1.f : 0.f;
        }
        out_black[e] = ((tbc / cnt) > 0.5f) ? 1.f : 0.f;
    }
}

// ---------------------------------------------------------------------------
extern "C" void kernel_launch(void* const* d_in, const int* in_sizes, int n_in,
                              void* d_out, int out_size)
{
    const float* start = (const float*)d_in[0];
    const float* end_p = (const float*)d_in[1];
    const float* imgs  = (const float*)d_in[2];
    const float* trans = (const float*)d_in[3];
    const float* K     = (const float*)d_in[4];
    const int*   npe   = (const int*)d_in[8];
    float* out = (float*)d_out;

    int n_edges = in_sizes[0] / 3;
    int P       = in_sizes[5];
    int num_src = in_sizes[3] / 12;  // 4
    int nimg    = num_src + 1;
    long long hw = (long long)in_sizes[2] / nimg;
    int W = (int)(sqrt((double)hw) + 0.5);
    int H = (int)(hw / W);

    float* out_loss  = out;
    float* out_mask  = out_loss + (size_t)num_src * n_edges;
    float* out_black = out_mask + (size_t)num_src * n_edges;
    float* out_p2d1  = out_black + n_edges;
    float* out_p2d2  = out_p2d1 + 2 * (size_t)P;

    int param_blocks = (n_edges + 255) / 256;
    int G = (H + 3) >> 2;
    int tile_total = nimg * G * W;
    int tile_blocks = (tile_total + 255) / 256;
    prep_tile_kernel<<<1 + param_blocks + tile_blocks, 256>>>(
        npe, start, end_p, K, trans, imgs,
        n_edges, num_src, 10.0f / (float)W, W, H, param_blocks);
    point_kernel<<<n_edges, 128>>>(npe,
                                   out_loss, out_mask, out_black,
                                   out_p2d1, out_p2d2,
                                   W, H, n_edges, P);
}

// round 17
// speedup vs baseline: 1.5491x; 1.0883x over previous
#include <cuda_runtime.h>
#include <cuda_fp16.h>
#include <math.h>

// ---------------------------------------------------------------------------
// Multi-view edge photometric loss.
// Output f32: loss(S,N) | mask(S,N) | black(N) | p2d1(P,2) | p2d2(S,P,2)
// Images re-tiled to FP16 with 8-row interleave: idx(x,y)=(y&~7)*W + 8x + (y&7)
// (half sector = 8 cols x 8 rows) -> warp gather footprint ~3 sectors.
// uv clamping via FFMA.SAT; masks via float min/max; outputs via st.global.cs.
// p2d outputs remain fp32-exact; fp16 only affects sampled intensities.
// ---------------------------------------------------------------------------

#define MAXE 6144
#define NS 4
#define NHV2 20
#define TIMGH_CAP (4 * 1024 * 1024)   // halfs (8 MB) — 5 x 800 x 800 = 3.2M fits

__device__ float4 g_params4[5 * MAXE * 2];  // per (cam,edge): p0x,p0y,dx,dy | ux,uy,-,-
__device__ int    g_begin[MAXE];
__device__ __half g_timgh[TIMGH_CAP];

__device__ __forceinline__ void stcs4(float4* p, float4 v) { __stcs(p, v); }

// ---------------- fused prep+tile: block-range dispatch --------------------
__device__ __forceinline__ void store_prm(int cam, int e, int nE,
                                          float p0x, float p0y,
                                          float dx, float dy, float upscale)
{
    float cx = dy, cy = -dx;
    float nrm = sqrtf(cx * cx + cy * cy);
    float sc = upscale / (nrm + 1e-6f);
    float* p = reinterpret_cast<float*>(&g_params4[((size_t)cam * nE + e) * 2]);
    p[0] = p0x; p[1] = p0y; p[2] = dx; p[3] = dy;
    p[4] = cx * sc; p[5] = cy * sc; p[6] = 0.f; p[7] = 0.f;
}

__global__ void prep_tile_kernel(const int* __restrict__ npe,
                                 const float* __restrict__ sp,
                                 const float* __restrict__ ep,
                                 const float* __restrict__ K,
                                 const float* __restrict__ trans,
                                 const float* __restrict__ imgs,
                                 int n_edges, int num_src, float upscale,
                                 int W, int H, int param_blocks)
{
    int blk = blockIdx.x;
    if (blk == 0) {
        __shared__ int ssum[256];
        int tid = threadIdx.x;
        int chunk = (n_edges + 255) / 256;
        int lo = min(tid * chunk, n_edges);
        int hi = min(lo + chunk, n_edges);
        int local = 0;
        for (int i = lo; i < hi; i++) local += npe[i];
        ssum[tid] = local;
        __syncthreads();
        for (int d = 1; d < 256; d <<= 1) {
            int t = (tid >= d) ? ssum[tid - d] : 0;
            __syncthreads();
            ssum[tid] += t;
            __syncthreads();
        }
        int run = ssum[tid] - local;
        for (int i = lo; i < hi; i++) { g_begin[i] = run; run += npe[i]; }
        return;
    }
    if (blk <= param_blocks) {
        int e = (blk - 1) * blockDim.x + threadIdx.x;
        if (e >= n_edges) return;
        float sx = sp[3 * e], sy = sp[3 * e + 1], sz = sp[3 * e + 2];
        float tx = ep[3 * e], ty = ep[3 * e + 1], tz = ep[3 * e + 2];
        {
            float pzs = K[6] * sx + K[7] * sy + K[8] * sz;
            float us  = (K[0] * sx + K[1] * sy + K[2] * sz) / (pzs + 1e-6f);
            float vs  = (K[3] * sx + K[4] * sy + K[5] * sz) / (pzs + 1e-6f);
            float pzt = K[6] * tx + K[7] * ty + K[8] * tz;
            float ut  = (K[0] * tx + K[1] * ty + K[2] * tz) / (pzt + 1e-6f);
            float vt  = (K[3] * tx + K[4] * ty + K[5] * tz) / (pzt + 1e-6f);
            store_prm(0, e, n_edges, us, vs, ut - us, vt - vs, upscale);
        }
        for (int s = 0; s < num_src; s++) {
            const float* T = trans + 12 * s;
            float pzs = T[8] * sx + T[9] * sy + T[10] * sz + T[11];
            float us  = (T[0] * sx + T[1] * sy + T[2] * sz + T[3]) / (pzs + 1e-6f);
            float vs  = (T[4] * sx + T[5] * sy + T[6] * sz + T[7]) / (pzs + 1e-6f);
            float pzt = T[8] * tx + T[9] * ty + T[10] * tz + T[11];
            float ut  = (T[0] * tx + T[1] * ty + T[2] * tz + T[3]) / (pzt + 1e-6f);
            float vt  = (T[4] * tx + T[5] * ty + T[6] * tz + T[7]) / (pzt + 1e-6f);
            store_prm(1 + s, e, n_edges, us, vs, ut - us, vt - vs, upscale);
        }
        return;
    }
    // tile pass: row-major f32 -> 8-row interleaved fp16
    int G = (H + 7) >> 3;
    int per = G * W;                      // 8-half slots per image
    int nimg = num_src + 1;
    int total = nimg * per;
    int idx = (blk - 1 - param_blocks) * blockDim.x + threadIdx.x;
    if (idx >= total) return;
    int c = idx / per;
    int rem = idx - c * per;
    int g = rem / W;
    int x = rem - g * W;
    const float* img = imgs + (size_t)c * W * H;
    __half hv[8];
    int y0 = g * 8;
#pragma unroll
    for (int k = 0; k < 8; k++) {
        int y = y0 + k;
        hv[k] = __float2half_rn((y < H) ? img[(size_t)y * W + x] : 0.f);
    }
    // 8 halfs = 16 B aligned slot
    reinterpret_cast<uint4*>(g_timgh)[(size_t)c * per + rem] =
        *reinterpret_cast<uint4*>(hv);
}

// ------------------- bilinear sample on fp16 tiled layout ------------------
// tiled idx(x,y) = (y & ~7)*W + 8x + (y & 7); u,v in [0,1] (saturated)
__device__ __forceinline__ float bilerp_h(const __half* __restrict__ timg,
                                          float u, float v, int W, int H)
{
    float x = fmaf(u, (float)W, -0.5f);
    float y = fmaf(v, (float)H, -0.5f);
    float x0f = floorf(x), y0f = floorf(y);
    float wx = x - x0f, wy = y - y0f;
    int x0 = max((int)x0f, 0);
    int x1 = min(x0 + 1, W - 1);      // u=1 -> x0=x1=W-1 (wx moot)
    int y0 = max((int)y0f, 0);
    int y1 = min(y0 + 1, H - 1);
    int base0 = (y0 & ~7) * W + (y0 & 7);
    int base1 = (y1 & ~7) * W + (y1 & 7);
    int xs0 = x0 << 3, xs1 = x1 << 3;
    float v00 = __half2float(__ldg(timg + (base0 + xs0)));
    float v01 = __half2float(__ldg(timg + (base0 + xs1)));
    float v10 = __half2float(__ldg(timg + (base1 + xs0)));
    float v11 = __half2float(__ldg(timg + (base1 + xs1)));
    float top = fmaf(wx, v01 - v00, v00);
    float bot = fmaf(wx, v11 - v10, v10);
    return fmaf(wy, bot - top, top);
}

// ----------- point kernel: block/edge, 128 thr, 2 points/thread ------------
__global__ void __launch_bounds__(128, 9)
point_kernel(const int* __restrict__ npe,
             float* __restrict__ out_loss, float* __restrict__ out_mask,
             float* __restrict__ out_black,
             float* __restrict__ out_p2d1, float* __restrict__ out_p2d2,
             int W, int H, int n_edges, int P)
{
    int e = blockIdx.x;
    int tid = threadIdx.x;

    __shared__ float4 sprm4[10];    // 5 cams x {p0x,p0y,dx,dy | ux,uy,-,-}
    __shared__ float redf[4][5];
    __shared__ unsigned redm[4];

    if (tid < 10) {
        int c = tid >> 1, half = tid & 1;
        sprm4[tid] = g_params4[((size_t)c * n_edges + e) * 2 + half];
    }
    __syncthreads();

    int b = g_begin[e];
    int n = npe[e];
    float inv_nh1 = 1.0f / (float)(n / NHV2 - 1);
    const int tstride = ((H + 7) >> 3) * 8 * W;   // per-image stride (halfs)

    float ls0 = 0.f, ls1 = 0.f, ls2 = 0.f, ls3 = 0.f;
    float bc = 0.f;
    unsigned m = (1u << NS) - 1u;

    float4* o1 = reinterpret_cast<float4*>(out_p2d1) + (b >> 1);
    float4* o2 = reinterpret_cast<float4*>(out_p2d2) + (b >> 1);
    const int strideP = P >> 1;

    int npair = n >> 1;
    // incremental (h, jj): r = h*10 + jj, r advances by 128 = 12*10 + 8
    int h  = tid / 10;
    int jj = tid - h * 10;
    for (int r = tid; r < npair; r += 128) {
        float cx = (float)h * inv_nh1;
        float base = (float)(2 * jj + ((jj < 5) ? -9 : -10));
        float cy0 = base * (1.0f / 9.0f);
        float cy1 = (base + 1.0f) * (1.0f / 9.0f);

        // reference camera: FFMA.SAT projections
        float4 qa = sprm4[0], qb = sprm4[1];
        float u0 = __saturatef(fmaf(qa.z, cx, fmaf(qb.x, cy0, qa.x)));
        float v0 = __saturatef(fmaf(qa.w, cx, fmaf(qb.y, cy0, qa.y)));
        float u1 = __saturatef(fmaf(qa.z, cx, fmaf(qb.x, cy1, qa.x)));
        float v1 = __saturatef(fmaf(qa.w, cx, fmaf(qb.y, cy1, qa.y)));
        float mn1 = fminf(fminf(u0, v0), fminf(u1, v1));
        float mx1 = fmaxf(fmaxf(u0, v0), fmaxf(u1, v1));
        stcs4(o1 + r, make_float4(u0, v0, u1, v1));
        float s1a = bilerp_h(g_timgh, u0, v0, W, H);
        float s1b = bilerp_h(g_timgh, u1, v1, W, H);
        bc += (s1a < 0.01f) ? 1.f : 0.f;
        bc += (s1b < 0.01f) ? 1.f : 0.f;

#pragma unroll
        for (int s = 0; s < NS; s++) {
            float4 pa = sprm4[2 * (s + 1)], pb = sprm4[2 * (s + 1) + 1];
            float ua = __saturatef(fmaf(pa.z, cx, fmaf(pb.x, cy0, pa.x)));
            float va = __saturatef(fmaf(pa.w, cx, fmaf(pb.y, cy0, pa.y)));
            float ub = __saturatef(fmaf(pa.z, cx, fmaf(pb.x, cy1, pa.x)));
            float vb = __saturatef(fmaf(pa.w, cx, fmaf(pb.y, cy1, pa.y)));
            float cmn = fminf(mn1, fminf(fminf(ua, va), fminf(ub, vb)));
            float cmx = fmaxf(mx1, fmaxf(fmaxf(ua, va), fmaxf(ub, vb)));
            stcs4(o2 + (s * strideP + r), make_float4(ua, va, ub, vb));
            const __half* img = g_timgh + (s + 1) * tstride;
            float s2a = bilerp_h(img, ua, va, W, H);
            float s2b = bilerp_h(img, ub, vb, W, H);
            float da = s2a - s1a;
            float db = s2b - s1b;
            float acc = fmaf(da, da, db * db);
            if (s == 0) ls0 += acc;
            else if (s == 1) ls1 += acc;
            else if (s == 2) ls2 += acc;
            else ls3 += acc;
            if (!((cmn > 0.f) & (cmx < 1.f))) m &= ~(1u << s);
        }

        jj += 8;
        if (jj >= 10) { jj -= 10; h += 13; } else { h += 12; }
    }

    // warp + block reduce
#pragma unroll
    for (int off = 16; off > 0; off >>= 1) {
        ls0 += __shfl_down_sync(0xFFFFFFFFu, ls0, off);
        ls1 += __shfl_down_sync(0xFFFFFFFFu, ls1, off);
        ls2 += __shfl_down_sync(0xFFFFFFFFu, ls2, off);
        ls3 += __shfl_down_sync(0xFFFFFFFFu, ls3, off);
        bc  += __shfl_down_sync(0xFFFFFFFFu, bc, off);
        m   &= __shfl_down_sync(0xFFFFFFFFu, m, off);
    }
    int lane = tid & 31, warp = tid >> 5;
    if (lane == 0) {
        redf[warp][0] = ls0; redf[warp][1] = ls1;
        redf[warp][2] = ls2; redf[warp][3] = ls3;
        redf[warp][4] = bc;
        redm[warp] = m;
    }
    __syncthreads();
    if (tid == 0) {
        float tls[NS] = {0.f, 0.f, 0.f, 0.f};
        float tbc = 0.f;
        unsigned tm = (1u << NS) - 1u;
        for (int w = 0; w < 4; w++) {
#pragma unroll
            for (int s = 0; s < NS; s++) tls[s] += redf[w][s];
            tbc += redf[w][4];
            tm &= redm[w];
        }
        float cnt = (float)n;
#pragma unroll
        for (int s = 0; s < NS; s++) {
            out_loss[s * n_edges + e] = tls[s] / cnt;
            out_mask[s * n_edges + e] = ((tm >> s) & 1u) ? 1.f : 0.f;
        }
        out_black[e] = ((tbc / cnt) > 0.5f) ? 1.f : 0.f;
    }
}

// ---------------------------------------------------------------------------
extern "C" void kernel_launch(void* const* d_in, const int* in_sizes, int n_in,
                              void* d_out, int out_size)
{
    const float* start = (const float*)d_in[0];
    const float* end_p = (const float*)d_in[1];
    const float* imgs  = (const float*)d_in[2];
    const float* trans = (const float*)d_in[3];
    const float* K     = (const float*)d_in[4];
    const int*   npe   = (const int*)d_in[8];
    float* out = (float*)d_out;

    int n_edges = in_sizes[0] / 3;
    int P       = in_sizes[5];
    int num_src = in_sizes[3] / 12;  // 4
    int nimg    = num_src + 1;
    long long hw = (long long)in_sizes[2] / nimg;
    int W = (int)(sqrt((double)hw) + 0.5);
    int H = (int)(hw / W);

    float* out_loss  = out;
    float* out_mask  = out_loss + (size_t)num_src * n_edges;
    float* out_black = out_mask + (size_t)num_src * n_edges;
    float* out_p2d1  = out_black + n_edges;
    float* out_p2d2  = out_p2d1 + 2 * (size_t)P;

    int param_blocks = (n_edges + 255) / 256;
    int G = (H + 7) >> 3;
    int tile_total = nimg * G * W;
    int tile_blocks = (tile_total + 255) / 256;
    prep_tile_kernel<<<1 + param_blocks + tile_blocks, 256>>>(
        npe, start, end_p, K, trans, imgs,
        n_edges, num_src, 10.0f / (float)W, W, H, param_blocks);
    point_kernel<<<n_edges, 128>>>(npe,
                                   out_loss, out_mask, out_black,
                                   out_p2d1, out_p2d2,
                                   W, H, n_edges, P);
}